// round 1
// baseline (speedup 1.0000x reference)
#include <cuda_runtime.h>

// NodeDenoisingADMM on sm_100a.
// Strategy: device-built CSR (no atomics in iteration loop), fused kernels:
//   k_phase1: Uk = (d*x + sum_l W_l @ T_l) / (d + mu2)        [row-parallel gather]
//   k_phase2: WU_l = W_l @ Uk (registers only) -> soft-threshold Q, dual Lam,
//             and next-iteration operand T_l = mu2' * Q + Lam'  (all fused)
// State layout interleaved [node][l][feat] so a per-edge gather of all 4
// operators is one contiguous 1KB region.

#define N_NODES 50000
#define FEAT    64
#define NNZQ    800000
#define LF      256   // L_OPS * FEAT

// ---------------- device scratch (no allocation allowed) ----------------
__device__ __align__(16) float g_T[N_NODES * LF];      // 51.2 MB
__device__ __align__(16) float g_Lam[N_NODES * LF];    // 51.2 MB
__device__ __align__(16) float g_Uk[N_NODES * FEAT];   // 12.8 MB
__device__ __align__(16) float g_ew[NNZQ * 4];         // 12.8 MB permuted weights
__device__ int g_ecol[NNZQ];                           // permuted col indices
__device__ int g_cnt[N_NODES];
__device__ int g_rowptr[N_NODES + 1];
__device__ int g_cursor[N_NODES];

// ---------------- CSR build ----------------
__global__ void k_zero_cnt() {
    int i = blockIdx.x * blockDim.x + threadIdx.x;
    if (i < N_NODES) g_cnt[i] = 0;
}

__global__ void k_count(const int* __restrict__ rows) {
    int e = blockIdx.x * blockDim.x + threadIdx.x;
    if (e < NNZQ) atomicAdd(&g_cnt[rows[e]], 1);
}

// Single-block exclusive scan over 50000 counts (chunked Hillis-Steele).
__global__ void k_scan() {
    __shared__ int ssum[1024];
    int t = threadIdx.x;
    const int chunk = (N_NODES + 1023) / 1024;  // 49
    int beg = t * chunk;
    int end = min(beg + chunk, N_NODES);
    int s = 0;
    for (int i = beg; i < end; i++) s += g_cnt[i];
    ssum[t] = s;
    __syncthreads();
    for (int off = 1; off < 1024; off <<= 1) {
        int v = (t >= off) ? ssum[t - off] : 0;
        __syncthreads();
        ssum[t] += v;
        __syncthreads();
    }
    int run = (t == 0) ? 0 : ssum[t - 1];
    for (int i = beg; i < end; i++) {
        g_rowptr[i] = run;
        g_cursor[i] = run;
        run += g_cnt[i];
    }
    if (end == N_NODES) g_rowptr[N_NODES] = run;
}

// Permute edges into row-sorted order; pack the 4 operator weights per edge.
__global__ void k_scatter(const int* __restrict__ rows, const int* __restrict__ cols,
                          const float* __restrict__ w) {
    int e = blockIdx.x * blockDim.x + threadIdx.x;
    if (e >= NNZQ) return;
    int r = rows[e];
    int p = atomicAdd(&g_cursor[r], 1);
    g_ecol[p] = cols[e];
    float4 wv;
    wv.x = w[e];
    wv.y = w[NNZQ + e];
    wv.z = w[2 * NNZQ + e];
    wv.w = w[3 * NNZQ + e];
    *(float4*)(g_ew + 4 * p) = wv;
}

// ---------------- iteration kernels ----------------

// iter 1 U-update: Q = Lam = 0 -> agg = 0 -> Uk = d/(d+mu2) * x  (mu2 = 1)
__global__ void k_init_u(const float* __restrict__ x, const float* __restrict__ d) {
    int i = blockIdx.x * blockDim.x + threadIdx.x;
    if (i < N_NODES * FEAT) {
        float dn = d[i >> 6];
        g_Uk[i] = dn / (dn + 1.0f) * x[i];
    }
}

// Phase 1 + U update. One warp per row; lane owns features (2*lane, 2*lane+1).
// out = final ? d_out : g_Uk
__global__ void k_phase1(const float* __restrict__ x, const float* __restrict__ d,
                         float* __restrict__ final_out, int is_final, float mu2) {
    int row = blockIdx.x * 8 + (threadIdx.x >> 5);
    if (row >= N_NODES) return;
    int lane = threadIdx.x & 31;
    int j0 = g_rowptr[row];
    int j1 = g_rowptr[row + 1];
    float a0 = 0.f, a1 = 0.f;
    const float* Tlane = g_T + lane * 2;
    for (int j = j0; j < j1; j++) {
        int c = g_ecol[j];
        float4 w = *(const float4*)(g_ew + 4 * j);
        const float* tp = Tlane + c * LF;
        float2 t0 = *(const float2*)(tp);
        float2 t1 = *(const float2*)(tp + 64);
        float2 t2 = *(const float2*)(tp + 128);
        float2 t3 = *(const float2*)(tp + 192);
        a0 += w.x * t0.x + w.y * t1.x + w.z * t2.x + w.w * t3.x;
        a1 += w.x * t0.y + w.y * t1.y + w.z * t2.y + w.w * t3.y;
    }
    float dr = d[row];
    float inv = 1.0f / (dr + mu2);
    int idx = row * FEAT + lane * 2;
    float2 xv = *(const float2*)(x + idx);
    float2 o;
    o.x = inv * (dr * xv.x + a0);
    o.y = inv * (dr * xv.y + a1);
    float* out = is_final ? final_out : g_Uk;
    *(float2*)(out + idx) = o;
}

// Phase 2 (WU in registers) + soft-threshold + dual update + next-iter T.
__global__ void k_phase2(const float* __restrict__ d,
                         float mu2, float mu2_next, int first) {
    int row = blockIdx.x * 8 + (threadIdx.x >> 5);
    if (row >= N_NODES) return;
    int lane = threadIdx.x & 31;
    int j0 = g_rowptr[row];
    int j1 = g_rowptr[row + 1];
    float acc[8];
#pragma unroll
    for (int i = 0; i < 8; i++) acc[i] = 0.f;
    const float* Ulane = g_Uk + lane * 2;
    for (int j = j0; j < j1; j++) {
        int c = g_ecol[j];
        float4 w = *(const float4*)(g_ew + 4 * j);
        float2 uv = *(const float2*)(Ulane + c * FEAT);
        acc[0] += w.x * uv.x;  acc[1] += w.x * uv.y;
        acc[2] += w.y * uv.x;  acc[3] += w.y * uv.y;
        acc[4] += w.z * uv.x;  acc[5] += w.z * uv.y;
        acc[6] += w.w * uv.x;  acc[7] += w.w * uv.y;
    }
    float dr = d[row];
    float inv_mu2 = 1.0f / mu2;
    const float nus[4] = {0.0f, 1.0f, 0.25f, 0.0625f};
    int base = row * LF + lane * 2;
#pragma unroll
    for (int l = 0; l < 4; l++) {
        float lamx = 0.f, lamy = 0.f;
        if (!first) {
            float2 lv = *(const float2*)(g_Lam + base + l * 64);
            lamx = lv.x; lamy = lv.y;
        }
        float eta = nus[l] * inv_mu2 * dr;
        float wux = acc[2 * l], wuy = acc[2 * l + 1];
        float xmx = wux - lamx * inv_mu2;
        float xmy = wuy - lamy * inv_mu2;
        float qx = fmaxf(xmx - eta, 0.f) - fmaxf(-xmx - eta, 0.f);
        float qy = fmaxf(xmy - eta, 0.f) - fmaxf(-xmy - eta, 0.f);
        float lnx = lamx + mu2 * (qx - wux);
        float lny = lamy + mu2 * (qy - wuy);
        *(float2*)(g_Lam + base + l * 64) = make_float2(lnx, lny);
        *(float2*)(g_T + base + l * 64) =
            make_float2(mu2_next * qx + lnx, mu2_next * qy + lny);
    }
}

// ---------------- launch ----------------
extern "C" void kernel_launch(void* const* d_in, const int* in_sizes, int n_in,
                              void* d_out, int out_size) {
    const float* x    = (const float*)d_in[0];
    const float* w    = (const float*)d_in[1];
    const float* d    = (const float*)d_in[2];
    const int*   rows = (const int*)d_in[3];
    const int*   cols = (const int*)d_in[4];
    float* out = (float*)d_out;

    const int GRID_R = (N_NODES + 7) / 8;  // warp per row, 8 rows/block

    // CSR build (per launch; deterministic work, order-only nondeterminism)
    k_zero_cnt<<<(N_NODES + 255) / 256, 256>>>();
    k_count<<<(NNZQ + 255) / 256, 256>>>(rows);
    k_scan<<<1, 1024>>>();
    k_scatter<<<(NNZQ + 255) / 256, 256>>>(rows, cols, w);

    // mu2 schedule: 1.0, 1.1, 1.21, 1.331, 1.4641
    const float m1 = 1.0f, m2 = 1.1f, m3 = 1.21f, m4 = 1.331f, m5 = 1.4641f;

    // iter 1: trivial U-update, then phase2 (Lam = 0)
    k_init_u<<<(N_NODES * FEAT + 255) / 256, 256>>>(x, d);
    k_phase2<<<GRID_R, 256>>>(d, m1, m2, 1);

    // iters 2-4: full
    k_phase1<<<GRID_R, 256>>>(x, d, out, 0, m2);
    k_phase2<<<GRID_R, 256>>>(d, m2, m3, 0);
    k_phase1<<<GRID_R, 256>>>(x, d, out, 0, m3);
    k_phase2<<<GRID_R, 256>>>(d, m3, m4, 0);
    k_phase1<<<GRID_R, 256>>>(x, d, out, 0, m4);
    k_phase2<<<GRID_R, 256>>>(d, m4, m5, 0);

    // iter 5: only the U-update matters; write straight to d_out
    k_phase1<<<GRID_R, 256>>>(x, d, out, 1, m5);
}

// round 2
// speedup vs baseline: 1.4444x; 1.4444x over previous
#include <cuda_runtime.h>
#include <cuda_fp16.h>

// NodeDenoisingADMM on sm_100a — R2: fp16 gathered state.
// T stored fp16 interleaved [node][featpair][l] -> one LDG.128 per edge-lane.
// Uk stored fp16 [node][featpair] for the phase-2 gather; fp32 only at final out.
// Lam stays fp32.

#define N_NODES 50000
#define FEAT    64
#define NNZQ    800000

// ---------------- device scratch ----------------
__device__ __align__(16) __half2 g_T16[N_NODES * 128];   // 25.6 MB  [node][pair][l]
__device__ __align__(16) __half2 g_U16[N_NODES * 32];    // 6.4 MB   [node][pair]
__device__ __align__(16) float   g_Lam[N_NODES * 256];   // 51.2 MB  [node][l][feat]
__device__ __align__(16) float   g_ew[NNZQ * 4];         // 12.8 MB  permuted weights
__device__ int g_ecol[NNZQ];
__device__ int g_cnt[N_NODES];
__device__ int g_rowptr[N_NODES + 1];
__device__ int g_cursor[N_NODES];

// ---------------- CSR build ----------------
__global__ void k_zero_cnt() {
    int i = blockIdx.x * blockDim.x + threadIdx.x;
    if (i < N_NODES) g_cnt[i] = 0;
}

__global__ void k_count(const int* __restrict__ rows) {
    int e = blockIdx.x * blockDim.x + threadIdx.x;
    if (e < NNZQ) atomicAdd(&g_cnt[rows[e]], 1);
}

__global__ void k_scan() {
    __shared__ int ssum[1024];
    int t = threadIdx.x;
    const int chunk = (N_NODES + 1023) / 1024;
    int beg = t * chunk;
    int end = min(beg + chunk, N_NODES);
    int s = 0;
    for (int i = beg; i < end; i++) s += g_cnt[i];
    ssum[t] = s;
    __syncthreads();
    for (int off = 1; off < 1024; off <<= 1) {
        int v = (t >= off) ? ssum[t - off] : 0;
        __syncthreads();
        ssum[t] += v;
        __syncthreads();
    }
    int run = (t == 0) ? 0 : ssum[t - 1];
    for (int i = beg; i < end; i++) {
        g_rowptr[i] = run;
        g_cursor[i] = run;
        run += g_cnt[i];
    }
    if (end == N_NODES) g_rowptr[N_NODES] = run;
}

__global__ void k_scatter(const int* __restrict__ rows, const int* __restrict__ cols,
                          const float* __restrict__ w) {
    int e = blockIdx.x * blockDim.x + threadIdx.x;
    if (e >= NNZQ) return;
    int r = rows[e];
    int p = atomicAdd(&g_cursor[r], 1);
    g_ecol[p] = cols[e];
    float4 wv;
    wv.x = w[e];
    wv.y = w[NNZQ + e];
    wv.z = w[2 * NNZQ + e];
    wv.w = w[3 * NNZQ + e];
    *(float4*)(g_ew + 4 * p) = wv;
}

// ---------------- iteration kernels ----------------

// iter 1 U-update (Q=Lam=0, mu2=1): U = d/(d+1) * x  -> fp16
__global__ void k_init_u(const float* __restrict__ x, const float* __restrict__ d) {
    int i = blockIdx.x * blockDim.x + threadIdx.x;   // feature-pair index
    if (i < N_NODES * 32) {
        float dn = d[i >> 5];
        float s = dn / (dn + 1.0f);
        float2 xv = *(const float2*)(x + i * 2);
        g_U16[i] = __floats2half2_rn(s * xv.x, s * xv.y);
    }
}

// Phase 1 + U update. Warp per row; lane owns feature pair `lane`.
__global__ void k_phase1(const float* __restrict__ x, const float* __restrict__ d,
                         float* __restrict__ final_out, int is_final, float mu2) {
    int row = blockIdx.x * 8 + (threadIdx.x >> 5);
    if (row >= N_NODES) return;
    int lane = threadIdx.x & 31;
    int j0 = g_rowptr[row];
    int j1 = g_rowptr[row + 1];
    float a0 = 0.f, a1 = 0.f;
#pragma unroll 2
    for (int j = j0; j < j1; j++) {
        int c = g_ecol[j];
        float4 w = *(const float4*)(g_ew + 4 * j);
        uint4 tv = *(const uint4*)(g_T16 + c * 128 + lane * 4);
        float2 t0 = __half22float2(*(__half2*)&tv.x);
        float2 t1 = __half22float2(*(__half2*)&tv.y);
        float2 t2 = __half22float2(*(__half2*)&tv.z);
        float2 t3 = __half22float2(*(__half2*)&tv.w);
        a0 += w.x * t0.x + w.y * t1.x + w.z * t2.x + w.w * t3.x;
        a1 += w.x * t0.y + w.y * t1.y + w.z * t2.y + w.w * t3.y;
    }
    float dr = d[row];
    float inv = 1.0f / (dr + mu2);
    int pidx = row * 32 + lane;
    float2 xv = *(const float2*)(x + pidx * 2);
    float ox = inv * (dr * xv.x + a0);
    float oy = inv * (dr * xv.y + a1);
    if (is_final) {
        *(float2*)(final_out + pidx * 2) = make_float2(ox, oy);
    } else {
        g_U16[pidx] = __floats2half2_rn(ox, oy);
    }
}

// Phase 2: WU in registers -> soft threshold Q -> dual Lam -> next-iter T (fp16).
__global__ void k_phase2(const float* __restrict__ d,
                         float mu2, float mu2_next, int first) {
    int row = blockIdx.x * 8 + (threadIdx.x >> 5);
    if (row >= N_NODES) return;
    int lane = threadIdx.x & 31;
    int j0 = g_rowptr[row];
    int j1 = g_rowptr[row + 1];
    float acc[8];
#pragma unroll
    for (int i = 0; i < 8; i++) acc[i] = 0.f;
#pragma unroll 2
    for (int j = j0; j < j1; j++) {
        int c = g_ecol[j];
        float4 w = *(const float4*)(g_ew + 4 * j);
        float2 uv = __half22float2(g_U16[c * 32 + lane]);
        acc[0] += w.x * uv.x;  acc[1] += w.x * uv.y;
        acc[2] += w.y * uv.x;  acc[3] += w.y * uv.y;
        acc[4] += w.z * uv.x;  acc[5] += w.z * uv.y;
        acc[6] += w.w * uv.x;  acc[7] += w.w * uv.y;
    }
    float dr = d[row];
    float inv_mu2 = 1.0f / mu2;
    const float nus[4] = {0.0f, 1.0f, 0.25f, 0.0625f};
    int lbase = row * 256 + lane * 2;
    __half2 tout[4];
#pragma unroll
    for (int l = 0; l < 4; l++) {
        float lamx = 0.f, lamy = 0.f;
        if (!first) {
            float2 lv = *(const float2*)(g_Lam + lbase + l * 64);
            lamx = lv.x; lamy = lv.y;
        }
        float eta = nus[l] * inv_mu2 * dr;
        float wux = acc[2 * l], wuy = acc[2 * l + 1];
        float xmx = wux - lamx * inv_mu2;
        float xmy = wuy - lamy * inv_mu2;
        float qx = fmaxf(xmx - eta, 0.f) - fmaxf(-xmx - eta, 0.f);
        float qy = fmaxf(xmy - eta, 0.f) - fmaxf(-xmy - eta, 0.f);
        float lnx = lamx + mu2 * (qx - wux);
        float lny = lamy + mu2 * (qy - wuy);
        *(float2*)(g_Lam + lbase + l * 64) = make_float2(lnx, lny);
        tout[l] = __floats2half2_rn(mu2_next * qx + lnx, mu2_next * qy + lny);
    }
    *(uint4*)(g_T16 + row * 128 + lane * 4) = *(uint4*)tout;
}

// ---------------- launch ----------------
extern "C" void kernel_launch(void* const* d_in, const int* in_sizes, int n_in,
                              void* d_out, int out_size) {
    const float* x    = (const float*)d_in[0];
    const float* w    = (const float*)d_in[1];
    const float* d    = (const float*)d_in[2];
    const int*   rows = (const int*)d_in[3];
    const int*   cols = (const int*)d_in[4];
    float* out = (float*)d_out;

    const int GRID_R = (N_NODES + 7) / 8;

    k_zero_cnt<<<(N_NODES + 255) / 256, 256>>>();
    k_count<<<(NNZQ + 255) / 256, 256>>>(rows);
    k_scan<<<1, 1024>>>();
    k_scatter<<<(NNZQ + 255) / 256, 256>>>(rows, cols, w);

    // mu2 schedule: 1.0, 1.1, 1.21, 1.331, 1.4641
    const float m1 = 1.0f, m2 = 1.1f, m3 = 1.21f, m4 = 1.331f, m5 = 1.4641f;

    k_init_u<<<(N_NODES * 32 + 255) / 256, 256>>>(x, d);
    k_phase2<<<GRID_R, 256>>>(d, m1, m2, 1);

    k_phase1<<<GRID_R, 256>>>(x, d, out, 0, m2);
    k_phase2<<<GRID_R, 256>>>(d, m2, m3, 0);
    k_phase1<<<GRID_R, 256>>>(x, d, out, 0, m3);
    k_phase2<<<GRID_R, 256>>>(d, m3, m4, 0);
    k_phase1<<<GRID_R, 256>>>(x, d, out, 0, m4);
    k_phase2<<<GRID_R, 256>>>(d, m4, m5, 0);

    k_phase1<<<GRID_R, 256>>>(x, d, out, 1, m5);
}